// round 1
// baseline (speedup 1.0000x reference)
#include <cuda_runtime.h>
#include <math.h>

#define N_NODES 40000
#define N_EDGES 640000
#define DIM     128
#define QKV_LD  384
#define HID     512
#define LN_EPS  1e-5f

// ---------------- scratch (device globals; no allocation allowed) ----------
static __device__ float g_qkv[(size_t)N_NODES * QKV_LD];  // [q|k|v] per node
static __device__ float g_rst[(size_t)N_NODES * DIM];     // post-LN1
static __device__ float g_h  [(size_t)N_NODES * HID];     // FFN hidden
static __device__ float g_y  [(size_t)N_NODES * DIM];     // pre-LN2
static __device__ int   g_off[N_NODES + 1];               // CSR offsets (by dst)
static __device__ int   g_cur[N_NODES];                   // counts / cursors
static __device__ int   g_eidx[N_EDGES];                  // edge ids sorted by dst

// ---------------- SGEMM: C[M,N] = A[M,K] @ B[K,N] (row-major) --------------
#define BM 64
#define BN 64
#define BK 16
#define TM 4
#define TN 4

// EPI: 0 = plain store, 1 = +bias then PReLU, 2 = +bias +residual
template <int EPI>
__global__ __launch_bounds__(256)
void sgemm_kernel(const float* __restrict__ A, int lda,
                  const float* __restrict__ B, int ldb,
                  float* __restrict__ C, int ldc, int K,
                  const float* __restrict__ bias,
                  const float* __restrict__ pw,
                  const float* __restrict__ res, int ldres)
{
    __shared__ float As[BK][BM];
    __shared__ float Bs[BK][BN];

    const int tid = threadIdx.x;
    const int m0 = (tid >> 4) * TM;       // 0..60
    const int n0 = (tid & 15) * TN;       // 0..60
    const int rowBase = blockIdx.x * BM;
    const int colBase = blockIdx.y * BN;

    const float* Ab = A + (size_t)rowBase * lda;
    const float* Bb = B + colBase;

    const int la_m = tid >> 2;            // 0..63
    const int la_k = (tid & 3) * 4;       // 0,4,8,12
    const int lb_k = tid >> 4;            // 0..15
    const int lb_n = (tid & 15) * 4;      // 0..60

    float acc[TM][TN];
#pragma unroll
    for (int i = 0; i < TM; i++)
#pragma unroll
        for (int j = 0; j < TN; j++) acc[i][j] = 0.f;

    for (int k0 = 0; k0 < K; k0 += BK) {
        float4 a4 = *(const float4*)(Ab + (size_t)la_m * lda + k0 + la_k);
        As[la_k + 0][la_m] = a4.x;
        As[la_k + 1][la_m] = a4.y;
        As[la_k + 2][la_m] = a4.z;
        As[la_k + 3][la_m] = a4.w;
        float4 b4 = *(const float4*)(Bb + (size_t)(k0 + lb_k) * ldb + lb_n);
        *(float4*)&Bs[lb_k][lb_n] = b4;
        __syncthreads();
#pragma unroll
        for (int kk = 0; kk < BK; kk++) {
            float a[TM], b[TN];
            *(float4*)a = *(const float4*)&As[kk][m0];
            *(float4*)b = *(const float4*)&Bs[kk][n0];
#pragma unroll
            for (int i = 0; i < TM; i++)
#pragma unroll
                for (int j = 0; j < TN; j++)
                    acc[i][j] += a[i] * b[j];
        }
        __syncthreads();
    }

    const int col = colBase + n0;
    float4 bia = make_float4(0, 0, 0, 0), pwv = make_float4(0, 0, 0, 0);
    if (EPI == 1 || EPI == 2) bia = *(const float4*)(bias + col);
    if (EPI == 1)             pwv = *(const float4*)(pw + col);

#pragma unroll
    for (int i = 0; i < TM; i++) {
        const int row = rowBase + m0 + i;
        float4 v = make_float4(acc[i][0], acc[i][1], acc[i][2], acc[i][3]);
        if (EPI == 1) {
            v.x += bia.x; v.y += bia.y; v.z += bia.z; v.w += bia.w;
            v.x = v.x >= 0.f ? v.x : pwv.x * v.x;
            v.y = v.y >= 0.f ? v.y : pwv.y * v.y;
            v.z = v.z >= 0.f ? v.z : pwv.z * v.z;
            v.w = v.w >= 0.f ? v.w : pwv.w * v.w;
        } else if (EPI == 2) {
            float4 r = *(const float4*)(res + (size_t)row * ldres + col);
            v.x += bia.x + r.x; v.y += bia.y + r.y;
            v.z += bia.z + r.z; v.w += bia.w + r.w;
        }
        *(float4*)(C + (size_t)row * ldc + col) = v;
    }
}

// ---------------- CSR construction -----------------------------------------
__global__ void zero_kernel()
{
    int i = blockIdx.x * blockDim.x + threadIdx.x;
    if (i < N_NODES) g_cur[i] = 0;
}

__global__ void hist_kernel(const int* __restrict__ dst, int e)
{
    int i = blockIdx.x * blockDim.x + threadIdx.x;
    if (i < e) atomicAdd(&g_cur[dst[i]], 1);
}

__global__ __launch_bounds__(1024)
void scan_kernel(int n)
{
    __shared__ int sh[1024];
    __shared__ int carry_s;
    const int tid = threadIdx.x;
    if (tid == 0) carry_s = 0;
    __syncthreads();
    for (int base = 0; base < n; base += 1024) {
        const int i = base + tid;
        const int v = (i < n) ? g_cur[i] : 0;
        sh[tid] = v;
        __syncthreads();
        for (int ofs = 1; ofs < 1024; ofs <<= 1) {
            int t = (tid >= ofs) ? sh[tid - ofs] : 0;
            __syncthreads();
            sh[tid] += t;
            __syncthreads();
        }
        const int excl = sh[tid] - v;
        const int c = carry_s;
        if (i < n) {
            g_off[i] = c + excl;
            g_cur[i] = c + excl;   // cursors for scatter
        }
        __syncthreads();
        if (tid == 1023) carry_s = c + sh[1023];
        __syncthreads();
    }
    if (tid == 0) g_off[n] = carry_s;
}

__global__ void scatter_kernel(const int* __restrict__ dst, int e)
{
    int i = blockIdx.x * blockDim.x + threadIdx.x;
    if (i < e) {
        int p = atomicAdd(&g_cur[dst[i]], 1);
        g_eidx[p] = i;
    }
}

// ---------------- attention (warp per dst node, online softmax) + LN1 ------
__global__ __launch_bounds__(256)
void attn_ln1_kernel(const float* __restrict__ feat,
                     const int* __restrict__ src,
                     const float* __restrict__ ln1g,
                     const float* __restrict__ ln1b)
{
    const int gw = (blockIdx.x * blockDim.x + threadIdx.x) >> 5;
    if (gw >= N_NODES) return;
    const int lane = threadIdx.x & 31;
    const int col = lane * 4;              // lane = h*4 + j ; col = h*16 + j*4

    const float* qrow = g_qkv + (size_t)gw * QKV_LD;
    const float4 q4 = *(const float4*)(qrow + col);

    float m = -INFINITY, s = 0.f;
    float4 acc = make_float4(0, 0, 0, 0);

    const int beg = g_off[gw], end = g_off[gw + 1];
    for (int t = beg; t < end; t++) {
        const int e = g_eidx[t];
        const int sv = src[e];
        const float* base = g_qkv + (size_t)sv * QKV_LD;
        const float4 k4 = *(const float4*)(base + DIM + col);
        float x = q4.x * k4.x + q4.y * k4.y + q4.z * k4.z + q4.w * k4.w;
        x += __shfl_xor_sync(0xffffffffu, x, 1);
        x += __shfl_xor_sync(0xffffffffu, x, 2);
        x *= 0.08838834764831845f;         // 1/sqrt(DH*H) = 1/sqrt(128)
        const float nm = fmaxf(m, x);
        const float corr = __expf(m - nm);
        const float w = __expf(x - nm);
        s = s * corr + w;
        const float4 v4 = *(const float4*)(base + 2 * DIM + col);
        acc.x = acc.x * corr + w * v4.x;
        acc.y = acc.y * corr + w * v4.y;
        acc.z = acc.z * corr + w * v4.z;
        acc.w = acc.w * corr + w * v4.w;
        m = nm;
    }

    const float inv = (s > 0.f) ? (1.f / s) : 0.f;
    const float4 f4 = *(const float4*)(feat + (size_t)gw * DIM + col);
    float x0 = acc.x * inv + f4.x;
    float x1 = acc.y * inv + f4.y;
    float x2 = acc.z * inv + f4.z;
    float x3 = acc.w * inv + f4.w;

    float sum = x0 + x1 + x2 + x3;
    float sq = x0 * x0 + x1 * x1 + x2 * x2 + x3 * x3;
#pragma unroll
    for (int o = 16; o; o >>= 1) {
        sum += __shfl_xor_sync(0xffffffffu, sum, o);
        sq  += __shfl_xor_sync(0xffffffffu, sq, o);
    }
    const float mu = sum * (1.f / DIM);
    const float var = sq * (1.f / DIM) - mu * mu;
    const float rstd = rsqrtf(var + LN_EPS);

    const float4 g4 = *(const float4*)(ln1g + col);
    const float4 b4 = *(const float4*)(ln1b + col);
    float4 o4;
    o4.x = (x0 - mu) * rstd * g4.x + b4.x;
    o4.y = (x1 - mu) * rstd * g4.y + b4.y;
    o4.z = (x2 - mu) * rstd * g4.z + b4.z;
    o4.w = (x3 - mu) * rstd * g4.w + b4.w;
    *(float4*)(g_rst + (size_t)gw * DIM + col) = o4;
}

// ---------------- final LN2 (warp per row) ----------------------------------
__global__ __launch_bounds__(256)
void ln2_kernel(const float* __restrict__ g,
                const float* __restrict__ b,
                float* __restrict__ out)
{
    const int gw = (blockIdx.x * blockDim.x + threadIdx.x) >> 5;
    if (gw >= N_NODES) return;
    const int lane = threadIdx.x & 31;
    const int col = lane * 4;

    const float4 x4 = *(const float4*)(g_y + (size_t)gw * DIM + col);
    float sum = x4.x + x4.y + x4.z + x4.w;
    float sq = x4.x * x4.x + x4.y * x4.y + x4.z * x4.z + x4.w * x4.w;
#pragma unroll
    for (int o = 16; o; o >>= 1) {
        sum += __shfl_xor_sync(0xffffffffu, sum, o);
        sq  += __shfl_xor_sync(0xffffffffu, sq, o);
    }
    const float mu = sum * (1.f / DIM);
    const float var = sq * (1.f / DIM) - mu * mu;
    const float rstd = rsqrtf(var + LN_EPS);

    const float4 g4 = *(const float4*)(g + col);
    const float4 b4 = *(const float4*)(b + col);
    float4 o4;
    o4.x = (x4.x - mu) * rstd * g4.x + b4.x;
    o4.y = (x4.y - mu) * rstd * g4.y + b4.y;
    o4.z = (x4.z - mu) * rstd * g4.z + b4.z;
    o4.w = (x4.w - mu) * rstd * g4.w + b4.w;
    *(float4*)(out + (size_t)gw * DIM + col) = o4;
}

// ---------------- launch -----------------------------------------------------
extern "C" void kernel_launch(void* const* d_in, const int* in_sizes, int n_in,
                              void* d_out, int out_size)
{
    const float* feat  = (const float*)d_in[0];
    const int*   src   = (const int*)d_in[1];
    const int*   dst   = (const int*)d_in[2];
    const float* Wq    = (const float*)d_in[3];
    const float* Wk    = (const float*)d_in[4];
    const float* Wv    = (const float*)d_in[5];
    const float* ln1g  = (const float*)d_in[6];
    const float* ln1b  = (const float*)d_in[7];
    const float* ln2g  = (const float*)d_in[8];
    const float* ln2b  = (const float*)d_in[9];
    const float* W1    = (const float*)d_in[10];
    const float* b1    = (const float*)d_in[11];
    const float* prelu = (const float*)d_in[12];
    const float* W2    = (const float*)d_in[13];
    const float* b2    = (const float*)d_in[14];
    float* out = (float*)d_out;

    const int E = in_sizes[1];

    void* p;
    float *qkv, *rst, *hbuf, *ybuf;
    cudaGetSymbolAddress(&p, g_qkv); qkv  = (float*)p;
    cudaGetSymbolAddress(&p, g_rst); rst  = (float*)p;
    cudaGetSymbolAddress(&p, g_h);   hbuf = (float*)p;
    cudaGetSymbolAddress(&p, g_y);   ybuf = (float*)p;

    // 1) QKV projections: three 40000x128x128 SGEMMs into interleaved [q|k|v]
    dim3 gqkv(N_NODES / BM, DIM / BN);
    sgemm_kernel<0><<<gqkv, 256>>>(feat, DIM, Wq, DIM, qkv + 0,       QKV_LD, DIM, nullptr, nullptr, nullptr, 0);
    sgemm_kernel<0><<<gqkv, 256>>>(feat, DIM, Wk, DIM, qkv + DIM,     QKV_LD, DIM, nullptr, nullptr, nullptr, 0);
    sgemm_kernel<0><<<gqkv, 256>>>(feat, DIM, Wv, DIM, qkv + 2 * DIM, QKV_LD, DIM, nullptr, nullptr, nullptr, 0);

    // 2) CSR by dst
    zero_kernel<<<(N_NODES + 255) / 256, 256>>>();
    hist_kernel<<<(E + 255) / 256, 256>>>(dst, E);
    scan_kernel<<<1, 1024>>>(N_NODES);
    scatter_kernel<<<(E + 255) / 256, 256>>>(dst, E);

    // 3) online-softmax attention + residual + LN1 (warp per dst node)
    attn_ln1_kernel<<<(N_NODES * 32 + 255) / 256, 256>>>(feat, src, ln1g, ln1b);

    // 4) FFN: h = PReLU(rst@W1 + b1); y = h@W2 + b2 + rst
    sgemm_kernel<1><<<dim3(N_NODES / BM, HID / BN), 256>>>(rst, DIM, W1, HID, hbuf, HID, DIM, b1, prelu, nullptr, 0);
    sgemm_kernel<2><<<dim3(N_NODES / BM, DIM / BN), 256>>>(hbuf, HID, W2, DIM, ybuf, DIM, HID, b2, nullptr, rst, DIM);

    // 5) LN2 -> out
    ln2_kernel<<<(N_NODES * 32 + 255) / 256, 256>>>(ln2g, ln2b, out);
}

// round 2
// speedup vs baseline: 1.4440x; 1.4440x over previous
#include <cuda_runtime.h>
#include <mma.h>
#include <math.h>

using namespace nvcuda;

#define N_NODES 40000
#define N_EDGES 640000
#define DIM     128
#define QKV_LD  384
#define HID     512
#define LN_EPS  1e-5f

// ---------------- scratch (device globals; no allocation allowed) ----------
static __device__ float g_qkv[(size_t)N_NODES * QKV_LD];  // [q|k|v] per node
static __device__ float g_rst[(size_t)N_NODES * DIM];     // post-LN1
static __device__ float g_h  [(size_t)N_NODES * HID];     // FFN hidden
static __device__ int   g_off[N_NODES + 1];               // CSR offsets (by dst)
static __device__ int   g_cur[N_NODES];                   // counts / cursors
static __device__ int   g_eidx[N_EDGES];                  // edge ids sorted by dst

// ---------------- TF32 WMMA GEMM: C[M,N] = A[M,K] @ B[K,N] (row-major) -----
// Tile: BM=64, BN=128, BK=32. 8 warps; warp tile 32x32 (2x2 wmma 16x16x8).
// EPI: 0 = plain store (QKV, B selected by blockIdx.z, C col offset z*128)
//      1 = +bias then PReLU
//      2 = +bias +residual, then per-row LayerNorm -> final output
#define GBM 64
#define GBN 128
#define GBK 32

template <int EPI>
__global__ __launch_bounds__(256)
void mm_tf32_kernel(const float* __restrict__ A, int lda,
                    const float* __restrict__ B0,
                    const float* __restrict__ B1,
                    const float* __restrict__ B2, int ldb,
                    float* __restrict__ C, int ldc, int K,
                    const float* __restrict__ bias,
                    const float* __restrict__ pw,
                    const float* __restrict__ res,
                    const float* __restrict__ lng,
                    const float* __restrict__ lnb)
{
    __shared__ __align__(16) float smem[64 * 132];      // 33792 B
    float (*As)[36]  = (float(*)[36]) smem;             // 64x36  (2304 f)
    float (*Bs)[132] = (float(*)[132])(smem + 2304);    // 32x132 (4224 f)
    float (*Cs)[132] = (float(*)[132]) smem;            // epilogue reuse

    const int tid = threadIdx.x;
    const int wid = tid >> 5;
    const int rowBase = blockIdx.x * GBM;
    const int colBaseB = blockIdx.y * GBN;               // col within B
    const int z = blockIdx.z;
    const float* B = (z == 0) ? B0 : (z == 1) ? B1 : B2;
    const int colBaseC = colBaseB + z * 128;             // col within C

    const int wm = wid >> 2;            // 0..1  -> warp row0 = wm*32
    const int wn = wid & 3;             // 0..3  -> warp col0 = wn*32

    wmma::fragment<wmma::accumulator, 16, 16, 8, float> acc[2][2];
#pragma unroll
    for (int i = 0; i < 2; i++)
#pragma unroll
        for (int j = 0; j < 2; j++) wmma::fill_fragment(acc[i][j], 0.f);

    // load indices
    const int ar = tid >> 3;            // 0..31 (A rows, 2 passes of 32)
    const int ac4 = (tid & 7) * 4;      // 0..28
    const int br = tid >> 5;            // 0..7  (B rows, 4 passes of 8)
    const int bc4 = (tid & 31) * 4;     // 0..124

    for (int k0 = 0; k0 < K; k0 += GBK) {
#pragma unroll
        for (int p = 0; p < 2; p++) {
            const int r = ar + p * 32;
            *(float4*)&As[r][ac4] =
                *(const float4*)(A + (size_t)(rowBase + r) * lda + k0 + ac4);
        }
#pragma unroll
        for (int p = 0; p < 4; p++) {
            const int r = br + p * 8;
            *(float4*)&Bs[r][bc4] =
                *(const float4*)(B + (size_t)(k0 + r) * ldb + colBaseB + bc4);
        }
        __syncthreads();

#pragma unroll
        for (int kk = 0; kk < GBK; kk += 8) {
            wmma::fragment<wmma::matrix_a, 16, 16, 8, wmma::precision::tf32, wmma::row_major> fa[2];
            wmma::fragment<wmma::matrix_b, 16, 16, 8, wmma::precision::tf32, wmma::row_major> fb[2];
#pragma unroll
            for (int i = 0; i < 2; i++) {
                wmma::load_matrix_sync(fa[i], &As[wm * 32 + i * 16][kk], 36);
#pragma unroll
                for (int t = 0; t < fa[i].num_elements; t++)
                    fa[i].x[t] = wmma::__float_to_tf32(fa[i].x[t]);
            }
#pragma unroll
            for (int j = 0; j < 2; j++) {
                wmma::load_matrix_sync(fb[j], &Bs[kk][wn * 32 + j * 16], 132);
#pragma unroll
                for (int t = 0; t < fb[j].num_elements; t++)
                    fb[j].x[t] = wmma::__float_to_tf32(fb[j].x[t]);
            }
#pragma unroll
            for (int i = 0; i < 2; i++)
#pragma unroll
                for (int j = 0; j < 2; j++)
                    wmma::mma_sync(acc[i][j], fa[i], fb[j], acc[i][j]);
        }
        __syncthreads();
    }

    // stage C tile in shared
#pragma unroll
    for (int i = 0; i < 2; i++)
#pragma unroll
        for (int j = 0; j < 2; j++)
            wmma::store_matrix_sync(&Cs[wm * 32 + i * 16][wn * 32 + j * 16],
                                    acc[i][j], 132, wmma::mem_row_major);
    __syncthreads();

    if (EPI == 0) {
#pragma unroll
        for (int it = 0; it < 8; it++) {
            const int lin = tid + it * 256;      // float4 index over 64x32
            const int r = lin >> 5, c4 = (lin & 31) * 4;
            *(float4*)(C + (size_t)(rowBase + r) * ldc + colBaseC + c4) =
                *(const float4*)&Cs[r][c4];
        }
    } else if (EPI == 1) {
#pragma unroll
        for (int it = 0; it < 8; it++) {
            const int lin = tid + it * 256;
            const int r = lin >> 5, c4 = (lin & 31) * 4;
            float4 v = *(const float4*)&Cs[r][c4];
            const float4 bi = *(const float4*)(bias + colBaseC + c4);
            const float4 pv = *(const float4*)(pw + colBaseC + c4);
            v.x += bi.x; v.y += bi.y; v.z += bi.z; v.w += bi.w;
            v.x = v.x >= 0.f ? v.x : pv.x * v.x;
            v.y = v.y >= 0.f ? v.y : pv.y * v.y;
            v.z = v.z >= 0.f ? v.z : pv.z * v.z;
            v.w = v.w >= 0.f ? v.w : pv.w * v.w;
            *(float4*)(C + (size_t)(rowBase + r) * ldc + colBaseC + c4) = v;
        }
    } else {  // EPI == 2 : +bias +residual, per-row LayerNorm -> out
        const int lane = tid & 31;
        const int col = lane * 4;
        const float4 bi = *(const float4*)(bias + col);
        const float4 g4 = *(const float4*)(lng + col);
        const float4 b4 = *(const float4*)(lnb + col);
#pragma unroll
        for (int rr = 0; rr < 8; rr++) {
            const int r = wid * 8 + rr;
            const int grow = rowBase + r;
            float4 v = *(const float4*)&Cs[r][col];
            const float4 rs = *(const float4*)(res + (size_t)grow * DIM + col);
            float x0 = v.x + bi.x + rs.x;
            float x1 = v.y + bi.y + rs.y;
            float x2 = v.z + bi.z + rs.z;
            float x3 = v.w + bi.w + rs.w;
            float sum = x0 + x1 + x2 + x3;
            float sq = x0 * x0 + x1 * x1 + x2 * x2 + x3 * x3;
#pragma unroll
            for (int o = 16; o; o >>= 1) {
                sum += __shfl_xor_sync(0xffffffffu, sum, o);
                sq  += __shfl_xor_sync(0xffffffffu, sq, o);
            }
            const float mu = sum * (1.f / DIM);
            const float var = sq * (1.f / DIM) - mu * mu;
            const float rstd = rsqrtf(var + LN_EPS);
            float4 o4;
            o4.x = (x0 - mu) * rstd * g4.x + b4.x;
            o4.y = (x1 - mu) * rstd * g4.y + b4.y;
            o4.z = (x2 - mu) * rstd * g4.z + b4.z;
            o4.w = (x3 - mu) * rstd * g4.w + b4.w;
            *(float4*)(C + (size_t)grow * DIM + col) = o4;
        }
    }
}

// ---------------- CSR construction -----------------------------------------
__global__ void zero_kernel()
{
    int i = blockIdx.x * blockDim.x + threadIdx.x;
    if (i < N_NODES) g_cur[i] = 0;
}

__global__ void hist_kernel(const int* __restrict__ dst, int e)
{
    int i = blockIdx.x * blockDim.x + threadIdx.x;
    if (i < e) atomicAdd(&g_cur[dst[i]], 1);
}

// 2-pass chunk scan: 1024 threads, 40 counts each, one block-level scan.
#define SCH 40
__global__ __launch_bounds__(1024)
void scan_kernel(int n)
{
    __shared__ int sh[1024];
    const int tid = threadIdx.x;
    const int base = tid * SCH;
    int tot = 0;
#pragma unroll 4
    for (int j = 0; j < SCH; j++) {
        const int i = base + j;
        tot += (i < n) ? g_cur[i] : 0;
    }
    sh[tid] = tot;
    __syncthreads();
    for (int ofs = 1; ofs < 1024; ofs <<= 1) {
        int t = (tid >= ofs) ? sh[tid - ofs] : 0;
        __syncthreads();
        sh[tid] += t;
        __syncthreads();
    }
    int run = sh[tid] - tot;
    if (tid == 1023) g_off[n] = sh[1023];
    for (int j = 0; j < SCH; j++) {
        const int i = base + j;
        if (i < n) {
            const int c = g_cur[i];
            g_off[i] = run;
            g_cur[i] = run;
            run += c;
        }
    }
}

__global__ void scatter_kernel(const int* __restrict__ dst, int e)
{
    int i = blockIdx.x * blockDim.x + threadIdx.x;
    if (i < e) {
        int p = atomicAdd(&g_cur[dst[i]], 1);
        g_eidx[p] = i;
    }
}

// ---------------- attention (warp per dst node, online softmax) + LN1 ------
__global__ __launch_bounds__(256)
void attn_ln1_kernel(const float* __restrict__ feat,
                     const int* __restrict__ src,
                     const float* __restrict__ ln1g,
                     const float* __restrict__ ln1b)
{
    const int gw = (blockIdx.x * blockDim.x + threadIdx.x) >> 5;
    if (gw >= N_NODES) return;
    const int lane = threadIdx.x & 31;
    const int col = lane * 4;              // lane = h*4 + j ; col = h*16 + j*4

    const float* qrow = g_qkv + (size_t)gw * QKV_LD;
    const float4 q4 = *(const float4*)(qrow + col);

    float m = -INFINITY, s = 0.f;
    float4 acc = make_float4(0, 0, 0, 0);

    const int beg = g_off[gw], end = g_off[gw + 1];
    for (int t = beg; t < end; t++) {
        const int e = g_eidx[t];
        const int sv = src[e];
        const float* base = g_qkv + (size_t)sv * QKV_LD;
        const float4 k4 = *(const float4*)(base + DIM + col);
        float x = q4.x * k4.x + q4.y * k4.y + q4.z * k4.z + q4.w * k4.w;
        x += __shfl_xor_sync(0xffffffffu, x, 1);
        x += __shfl_xor_sync(0xffffffffu, x, 2);
        x *= 0.08838834764831845f;         // 1/sqrt(DH*H) = 1/sqrt(128)
        const float nm = fmaxf(m, x);
        const float corr = __expf(m - nm);
        const float w = __expf(x - nm);
        s = s * corr + w;
        const float4 v4 = *(const float4*)(base + 2 * DIM + col);
        acc.x = acc.x * corr + w * v4.x;
        acc.y = acc.y * corr + w * v4.y;
        acc.z = acc.z * corr + w * v4.z;
        acc.w = acc.w * corr + w * v4.w;
        m = nm;
    }

    const float inv = (s > 0.f) ? (1.f / s) : 0.f;
    const float4 f4 = *(const float4*)(feat + (size_t)gw * DIM + col);
    float x0 = acc.x * inv + f4.x;
    float x1 = acc.y * inv + f4.y;
    float x2 = acc.z * inv + f4.z;
    float x3 = acc.w * inv + f4.w;

    float sum = x0 + x1 + x2 + x3;
    float sq = x0 * x0 + x1 * x1 + x2 * x2 + x3 * x3;
#pragma unroll
    for (int o = 16; o; o >>= 1) {
        sum += __shfl_xor_sync(0xffffffffu, sum, o);
        sq  += __shfl_xor_sync(0xffffffffu, sq, o);
    }
    const float mu = sum * (1.f / DIM);
    const float var = sq * (1.f / DIM) - mu * mu;
    const float rstd = rsqrtf(var + LN_EPS);

    const float4 g4 = *(const float4*)(ln1g + col);
    const float4 b4 = *(const float4*)(ln1b + col);
    float4 o4;
    o4.x = (x0 - mu) * rstd * g4.x + b4.x;
    o4.y = (x1 - mu) * rstd * g4.y + b4.y;
    o4.z = (x2 - mu) * rstd * g4.z + b4.z;
    o4.w = (x3 - mu) * rstd * g4.w + b4.w;
    *(float4*)(g_rst + (size_t)gw * DIM + col) = o4;
}

// ---------------- launch -----------------------------------------------------
extern "C" void kernel_launch(void* const* d_in, const int* in_sizes, int n_in,
                              void* d_out, int out_size)
{
    const float* feat  = (const float*)d_in[0];
    const int*   src   = (const int*)d_in[1];
    const int*   dst   = (const int*)d_in[2];
    const float* Wq    = (const float*)d_in[3];
    const float* Wk    = (const float*)d_in[4];
    const float* Wv    = (const float*)d_in[5];
    const float* ln1g  = (const float*)d_in[6];
    const float* ln1b  = (const float*)d_in[7];
    const float* ln2g  = (const float*)d_in[8];
    const float* ln2b  = (const float*)d_in[9];
    const float* W1    = (const float*)d_in[10];
    const float* b1    = (const float*)d_in[11];
    const float* prelu = (const float*)d_in[12];
    const float* W2    = (const float*)d_in[13];
    const float* b2    = (const float*)d_in[14];
    float* out = (float*)d_out;

    const int E = in_sizes[1];

    void* p;
    float *qkv, *rst, *hbuf;
    cudaGetSymbolAddress(&p, g_qkv); qkv  = (float*)p;
    cudaGetSymbolAddress(&p, g_rst); rst  = (float*)p;
    cudaGetSymbolAddress(&p, g_h);   hbuf = (float*)p;

    // 1) fused QKV projections (TF32 tensor cores), one launch, grid.z = 3
    mm_tf32_kernel<0><<<dim3(N_NODES / GBM, 1, 3), 256>>>(
        feat, DIM, Wq, Wk, Wv, DIM, qkv, QKV_LD, DIM,
        nullptr, nullptr, nullptr, nullptr, nullptr);

    // 2) CSR by dst
    zero_kernel<<<(N_NODES + 255) / 256, 256>>>();
    hist_kernel<<<(E + 255) / 256, 256>>>(dst, E);
    scan_kernel<<<1, 1024>>>(N_NODES);
    scatter_kernel<<<(E + 255) / 256, 256>>>(dst, E);

    // 3) online-softmax attention + residual + LN1 (warp per dst node)
    attn_ln1_kernel<<<(N_NODES * 32 + 255) / 256, 256>>>(feat, src, ln1g, ln1b);

    // 4) FFN1: h = PReLU(rst@W1 + b1)
    mm_tf32_kernel<1><<<dim3(N_NODES / GBM, HID / GBN, 1), 256>>>(
        rst, DIM, W1, W1, W1, HID, hbuf, HID, DIM,
        b1, prelu, nullptr, nullptr, nullptr);

    // 5) FFN2 + bias + residual + LN2 -> out (fused epilogue)
    mm_tf32_kernel<2><<<dim3(N_NODES / GBM, 1, 1), 256>>>(
        hbuf, HID, W2, W2, W2, DIM, out, DIM, HID,
        b2, nullptr, rst, ln2g, ln2b);
}

// round 3
// speedup vs baseline: 1.7946x; 1.2428x over previous
#include <cuda_runtime.h>
#include <mma.h>
#include <math.h>

using namespace nvcuda;

#define N_NODES 40000
#define N_EDGES 640000
#define DIM     128
#define QKV_LD  384
#define HID     512
#define LN_EPS  1e-5f

// ---------------- scratch (device globals; no allocation allowed) ----------
static __device__ float g_qkv[(size_t)N_NODES * QKV_LD];  // [q|k|v] per node
static __device__ float g_rst[(size_t)N_NODES * DIM];     // post-LN1
static __device__ float g_h  [(size_t)N_NODES * HID];     // FFN hidden
static __device__ int   g_off[N_NODES + 1];               // CSR offsets (by dst)
static __device__ int   g_cur[N_NODES];                   // counts / cursors
static __device__ int   g_eidx[N_EDGES];                  // edge ids sorted by dst
static __device__ int   g_part[256];                      // scan partials

// ---------------- cp.async helpers -----------------------------------------
__device__ __forceinline__ void cp16(float* smem, const float* gmem)
{
    unsigned s = (unsigned)__cvta_generic_to_shared(smem);
    asm volatile("cp.async.ca.shared.global [%0], [%1], 16;\n" :: "r"(s), "l"(gmem));
}
#define CP_COMMIT() asm volatile("cp.async.commit_group;\n" ::)
#define CP_WAIT(n)  asm volatile("cp.async.wait_group %0;\n" :: "n"(n))

// ---------------- TF32 WMMA GEMM: C[M,N] = A[M,K] @ B[K,N] (row-major) -----
// Tile: BM=64, BN=128, BK=32, 2-stage cp.async double buffer.
// 8 warps; warp tile 32x32 (2x2 wmma 16x16x8).
// EPI: 0 = plain store (QKV: B selected by blockIdx.z, C col offset z*128)
//      1 = +bias then PReLU
//      2 = +bias +residual, then per-row LayerNorm -> final output
#define GBM 64
#define GBN 128
#define GBK 32
#define AS_F (64 * 36)     // 2304 floats / stage
#define BS_F (32 * 132)    // 4224 floats / stage
#define SMEM_BYTES ((2 * AS_F + 2 * BS_F) * 4)   // 52224 B

template <int EPI>
__global__ __launch_bounds__(256)
void mm_tf32_kernel(const float* __restrict__ A, int lda,
                    const float* __restrict__ B0,
                    const float* __restrict__ B1,
                    const float* __restrict__ B2, int ldb,
                    float* __restrict__ C, int ldc, int K,
                    const float* __restrict__ bias,
                    const float* __restrict__ pw,
                    const float* __restrict__ res,
                    const float* __restrict__ lng,
                    const float* __restrict__ lnb)
{
    extern __shared__ __align__(16) float sm[];
    float* AsBuf[2] = { sm, sm + AS_F };
    float* BsBuf[2] = { sm + 2 * AS_F, sm + 2 * AS_F + BS_F };
    float (*Cs)[132] = (float(*)[132]) sm;        // epilogue reuse

    const int tid = threadIdx.x;
    const int wid = tid >> 5;
    const int rowBase = blockIdx.x * GBM;
    const int colBaseB = blockIdx.y * GBN;
    const int z = blockIdx.z;
    const float* B = (z == 0) ? B0 : (z == 1) ? B1 : B2;
    const int colBaseC = colBaseB + z * 128;

    const int wm = wid >> 2;            // 0..1
    const int wn = wid & 3;             // 0..3

    wmma::fragment<wmma::accumulator, 16, 16, 8, float> acc[2][2];
#pragma unroll
    for (int i = 0; i < 2; i++)
#pragma unroll
        for (int j = 0; j < 2; j++) wmma::fill_fragment(acc[i][j], 0.f);

    const int ar = tid >> 3;            // 0..31
    const int ac = (tid & 7) * 4;       // 0..28
    const int br = tid >> 5;            // 0..7
    const int bc = (tid & 31) * 4;      // 0..124

    const float* Abase = A + (size_t)rowBase * lda;
    const float* Bbase = B + colBaseB;

    // stage loader
    auto issue = [&](int st, int k0) {
        float* As = AsBuf[st];
        float* Bs = BsBuf[st];
#pragma unroll
        for (int p = 0; p < 2; p++) {
            const int r = ar + p * 32;
            cp16(As + r * 36 + ac, Abase + (size_t)r * lda + k0 + ac);
        }
#pragma unroll
        for (int p = 0; p < 4; p++) {
            const int r = br + p * 8;
            cp16(Bs + r * 132 + bc, Bbase + (size_t)(k0 + r) * ldb + bc);
        }
        CP_COMMIT();
    };

    issue(0, 0);
    const int nIter = K / GBK;

    for (int it = 0; it < nIter; it++) {
        const bool more = (it + 1 < nIter);
        if (more) issue((it + 1) & 1, (it + 1) * GBK);
        if (more) CP_WAIT(1); else CP_WAIT(0);
        __syncthreads();

        const float* As = AsBuf[it & 1];
        const float* Bs = BsBuf[it & 1];
#pragma unroll
        for (int kk = 0; kk < GBK; kk += 8) {
            wmma::fragment<wmma::matrix_a, 16, 16, 8, wmma::precision::tf32, wmma::row_major> fa[2];
            wmma::fragment<wmma::matrix_b, 16, 16, 8, wmma::precision::tf32, wmma::row_major> fb[2];
#pragma unroll
            for (int i = 0; i < 2; i++)
                wmma::load_matrix_sync(fa[i], As + (wm * 32 + i * 16) * 36 + kk, 36);
#pragma unroll
            for (int j = 0; j < 2; j++)
                wmma::load_matrix_sync(fb[j], Bs + kk * 132 + wn * 32 + j * 16, 132);
#pragma unroll
            for (int i = 0; i < 2; i++)
#pragma unroll
                for (int j = 0; j < 2; j++)
                    wmma::mma_sync(acc[i][j], fa[i], fb[j], acc[i][j]);
        }
        __syncthreads();
    }

    // stage C tile in shared
#pragma unroll
    for (int i = 0; i < 2; i++)
#pragma unroll
        for (int j = 0; j < 2; j++)
            wmma::store_matrix_sync(&Cs[wm * 32 + i * 16][wn * 32 + j * 16],
                                    acc[i][j], 132, wmma::mem_row_major);
    __syncthreads();

    if (EPI == 0) {
#pragma unroll
        for (int it = 0; it < 8; it++) {
            const int lin = tid + it * 256;
            const int r = lin >> 5, c4 = (lin & 31) * 4;
            *(float4*)(C + (size_t)(rowBase + r) * ldc + colBaseC + c4) =
                *(const float4*)&Cs[r][c4];
        }
    } else if (EPI == 1) {
#pragma unroll
        for (int it = 0; it < 8; it++) {
            const int lin = tid + it * 256;
            const int r = lin >> 5, c4 = (lin & 31) * 4;
            float4 v = *(const float4*)&Cs[r][c4];
            const float4 bi = *(const float4*)(bias + colBaseC + c4);
            const float4 pv = *(const float4*)(pw + colBaseC + c4);
            v.x += bi.x; v.y += bi.y; v.z += bi.z; v.w += bi.w;
            v.x = v.x >= 0.f ? v.x : pv.x * v.x;
            v.y = v.y >= 0.f ? v.y : pv.y * v.y;
            v.z = v.z >= 0.f ? v.z : pv.z * v.z;
            v.w = v.w >= 0.f ? v.w : pv.w * v.w;
            *(float4*)(C + (size_t)(rowBase + r) * ldc + colBaseC + c4) = v;
        }
    } else {  // EPI == 2 : +bias +residual, per-row LayerNorm -> out
        const int lane = tid & 31;
        const int col = lane * 4;
        const float4 bi = *(const float4*)(bias + col);
        const float4 g4 = *(const float4*)(lng + col);
        const float4 b4 = *(const float4*)(lnb + col);
#pragma unroll
        for (int rr = 0; rr < 8; rr++) {
            const int r = wid * 8 + rr;
            const int grow = rowBase + r;
            float4 v = *(const float4*)&Cs[r][col];
            const float4 rs = *(const float4*)(res + (size_t)grow * DIM + col);
            float x0 = v.x + bi.x + rs.x;
            float x1 = v.y + bi.y + rs.y;
            float x2 = v.z + bi.z + rs.z;
            float x3 = v.w + bi.w + rs.w;
            float sum = x0 + x1 + x2 + x3;
            float sq = x0 * x0 + x1 * x1 + x2 * x2 + x3 * x3;
#pragma unroll
            for (int o = 16; o; o >>= 1) {
                sum += __shfl_xor_sync(0xffffffffu, sum, o);
                sq  += __shfl_xor_sync(0xffffffffu, sq, o);
            }
            const float mu = sum * (1.f / DIM);
            const float var = sq * (1.f / DIM) - mu * mu;
            const float rstd = rsqrtf(var + LN_EPS);
            float4 o4;
            o4.x = (x0 - mu) * rstd * g4.x + b4.x;
            o4.y = (x1 - mu) * rstd * g4.y + b4.y;
            o4.z = (x2 - mu) * rstd * g4.z + b4.z;
            o4.w = (x3 - mu) * rstd * g4.w + b4.w;
            *(float4*)(C + (size_t)grow * DIM + col) = o4;
        }
    }
}

// ---------------- CSR construction -----------------------------------------
__global__ void hist_kernel(const int* __restrict__ dst, int e)
{
    int i = blockIdx.x * blockDim.x + threadIdx.x;
    if (i < e) atomicAdd(&g_cur[dst[i]], 1);
}

#define SB 256
#define NSB ((N_NODES + SB - 1) / SB)   // 157

__global__ __launch_bounds__(SB)
void scan_blk_kernel(int n)
{
    __shared__ int sh[SB];
    const int t = threadIdx.x;
    const int i = blockIdx.x * SB + t;
    const int v = (i < n) ? g_cur[i] : 0;
    sh[t] = v;
    __syncthreads();
    for (int o = 1; o < SB; o <<= 1) {
        int x = (t >= o) ? sh[t - o] : 0;
        __syncthreads();
        sh[t] += x;
        __syncthreads();
    }
    if (i < n) g_off[i] = sh[t] - v;          // local exclusive
    if (t == SB - 1) g_part[blockIdx.x] = sh[t];
}

__global__ __launch_bounds__(SB)
void scan_part_kernel(int nb, int n)
{
    __shared__ int sh[SB];
    const int t = threadIdx.x;
    const int v = (t < nb) ? g_part[t] : 0;
    sh[t] = v;
    __syncthreads();
    for (int o = 1; o < SB; o <<= 1) {
        int x = (t >= o) ? sh[t - o] : 0;
        __syncthreads();
        sh[t] += x;
        __syncthreads();
    }
    if (t < nb) g_part[t] = sh[t] - v;        // exclusive
    if (t == SB - 1) g_off[n] = sh[t];        // grand total
}

__global__ __launch_bounds__(SB)
void scan_add_kernel(int n)
{
    const int i = blockIdx.x * SB + threadIdx.x;
    if (i < n) {
        const int o = g_off[i] + g_part[blockIdx.x];
        g_off[i] = o;
        g_cur[i] = o;
    }
}

__global__ void scatter_kernel(const int* __restrict__ dst, int e)
{
    int i = blockIdx.x * blockDim.x + threadIdx.x;
    if (i < e) {
        int p = atomicAdd(&g_cur[dst[i]], 1);
        g_eidx[p] = i;
    }
}

// ---------------- attention (warp per dst node, online softmax) + LN1 ------
__device__ __forceinline__ void attn_step(float4 k4, float4 v4, float4 q4,
                                          float& m, float& s, float4& acc)
{
    float x = q4.x * k4.x + q4.y * k4.y + q4.z * k4.z + q4.w * k4.w;
    x += __shfl_xor_sync(0xffffffffu, x, 1);
    x += __shfl_xor_sync(0xffffffffu, x, 2);
    x *= 0.08838834764831845f;              // 1/sqrt(DH*H) = 1/sqrt(128)
    const float nm = fmaxf(m, x);
    const float corr = __expf(m - nm);
    const float w = __expf(x - nm);
    s = s * corr + w;
    acc.x = acc.x * corr + w * v4.x;
    acc.y = acc.y * corr + w * v4.y;
    acc.z = acc.z * corr + w * v4.z;
    acc.w = acc.w * corr + w * v4.w;
    m = nm;
}

__global__ __launch_bounds__(256)
void attn_ln1_kernel(const float* __restrict__ feat,
                     const int* __restrict__ src,
                     const float* __restrict__ ln1g,
                     const float* __restrict__ ln1b)
{
    const int gw = (blockIdx.x * blockDim.x + threadIdx.x) >> 5;
    if (gw >= N_NODES) return;
    const int lane = threadIdx.x & 31;
    const int col = lane * 4;

    const float4 q4 = *(const float4*)(g_qkv + (size_t)gw * QKV_LD + col);

    float m = -INFINITY, s = 0.f;
    float4 acc = make_float4(0, 0, 0, 0);

    const int beg = g_off[gw], end = g_off[gw + 1];
    int t = beg;
    // unrolled-by-4: batch the 3-level dependent loads for MLP=4
    for (; t + 4 <= end; t += 4) {
        const int e0 = g_eidx[t], e1 = g_eidx[t + 1];
        const int e2 = g_eidx[t + 2], e3 = g_eidx[t + 3];
        const int s0 = src[e0], s1 = src[e1], s2 = src[e2], s3 = src[e3];
        const float* b0 = g_qkv + (size_t)s0 * QKV_LD + col;
        const float* b1 = g_qkv + (size_t)s1 * QKV_LD + col;
        const float* b2 = g_qkv + (size_t)s2 * QKV_LD + col;
        const float* b3 = g_qkv + (size_t)s3 * QKV_LD + col;
        const float4 k0 = *(const float4*)(b0 + DIM);
        const float4 k1 = *(const float4*)(b1 + DIM);
        const float4 k2 = *(const float4*)(b2 + DIM);
        const float4 k3 = *(const float4*)(b3 + DIM);
        const float4 v0 = *(const float4*)(b0 + 2 * DIM);
        const float4 v1 = *(const float4*)(b1 + 2 * DIM);
        const float4 v2 = *(const float4*)(b2 + 2 * DIM);
        const float4 v3 = *(const float4*)(b3 + 2 * DIM);
        attn_step(k0, v0, q4, m, s, acc);
        attn_step(k1, v1, q4, m, s, acc);
        attn_step(k2, v2, q4, m, s, acc);
        attn_step(k3, v3, q4, m, s, acc);
    }
    for (; t < end; t++) {
        const int e = g_eidx[t];
        const float* b = g_qkv + (size_t)src[e] * QKV_LD + col;
        const float4 k4 = *(const float4*)(b + DIM);
        const float4 v4 = *(const float4*)(b + 2 * DIM);
        attn_step(k4, v4, q4, m, s, acc);
    }

    const float inv = (s > 0.f) ? (1.f / s) : 0.f;
    const float4 f4 = *(const float4*)(feat + (size_t)gw * DIM + col);
    float x0 = acc.x * inv + f4.x;
    float x1 = acc.y * inv + f4.y;
    float x2 = acc.z * inv + f4.z;
    float x3 = acc.w * inv + f4.w;

    float sum = x0 + x1 + x2 + x3;
    float sq = x0 * x0 + x1 * x1 + x2 * x2 + x3 * x3;
#pragma unroll
    for (int o = 16; o; o >>= 1) {
        sum += __shfl_xor_sync(0xffffffffu, sum, o);
        sq  += __shfl_xor_sync(0xffffffffu, sq, o);
    }
    const float mu = sum * (1.f / DIM);
    const float var = sq * (1.f / DIM) - mu * mu;
    const float rstd = rsqrtf(var + LN_EPS);

    const float4 g4 = *(const float4*)(ln1g + col);
    const float4 b4 = *(const float4*)(ln1b + col);
    float4 o4;
    o4.x = (x0 - mu) * rstd * g4.x + b4.x;
    o4.y = (x1 - mu) * rstd * g4.y + b4.y;
    o4.z = (x2 - mu) * rstd * g4.z + b4.z;
    o4.w = (x3 - mu) * rstd * g4.w + b4.w;
    *(float4*)(g_rst + (size_t)gw * DIM + col) = o4;
}

// ---------------- launch -----------------------------------------------------
extern "C" void kernel_launch(void* const* d_in, const int* in_sizes, int n_in,
                              void* d_out, int out_size)
{
    const float* feat  = (const float*)d_in[0];
    const int*   src   = (const int*)d_in[1];
    const int*   dst   = (const int*)d_in[2];
    const float* Wq    = (const float*)d_in[3];
    const float* Wk    = (const float*)d_in[4];
    const float* Wv    = (const float*)d_in[5];
    const float* ln1g  = (const float*)d_in[6];
    const float* ln1b  = (const float*)d_in[7];
    const float* ln2g  = (const float*)d_in[8];
    const float* ln2b  = (const float*)d_in[9];
    const float* W1    = (const float*)d_in[10];
    const float* b1    = (const float*)d_in[11];
    const float* prelu = (const float*)d_in[12];
    const float* W2    = (const float*)d_in[13];
    const float* b2    = (const float*)d_in[14];
    float* out = (float*)d_out;

    const int E = in_sizes[1];

    void* p;
    float *qkv, *rst, *hbuf;
    int* curp;
    cudaGetSymbolAddress(&p, g_qkv); qkv  = (float*)p;
    cudaGetSymbolAddress(&p, g_rst); rst  = (float*)p;
    cudaGetSymbolAddress(&p, g_h);   hbuf = (float*)p;
    cudaGetSymbolAddress(&p, g_cur); curp = (int*)p;

    cudaFuncSetAttribute(mm_tf32_kernel<0>, cudaFuncAttributeMaxDynamicSharedMemorySize, SMEM_BYTES);
    cudaFuncSetAttribute(mm_tf32_kernel<1>, cudaFuncAttributeMaxDynamicSharedMemorySize, SMEM_BYTES);
    cudaFuncSetAttribute(mm_tf32_kernel<2>, cudaFuncAttributeMaxDynamicSharedMemorySize, SMEM_BYTES);

    // 1) fused QKV projections (TF32 tensor cores), one launch, grid.z = 3
    mm_tf32_kernel<0><<<dim3(N_NODES / GBM, 1, 3), 256, SMEM_BYTES>>>(
        feat, DIM, Wq, Wk, Wv, DIM, qkv, QKV_LD, DIM,
        nullptr, nullptr, nullptr, nullptr, nullptr);

    // 2) CSR by dst
    cudaMemsetAsync(curp, 0, N_NODES * sizeof(int));
    hist_kernel<<<(E + 255) / 256, 256>>>(dst, E);
    scan_blk_kernel<<<NSB, SB>>>(N_NODES);
    scan_part_kernel<<<1, SB>>>(NSB, N_NODES);
    scan_add_kernel<<<NSB, SB>>>(N_NODES);
    scatter_kernel<<<(E + 255) / 256, 256>>>(dst, E);

    // 3) online-softmax attention + residual + LN1 (warp per dst node)
    attn_ln1_kernel<<<(N_NODES * 32 + 255) / 256, 256>>>(feat, src, ln1g, ln1b);

    // 4) FFN1: h = PReLU(rst@W1 + b1)
    mm_tf32_kernel<1><<<dim3(N_NODES / GBM, HID / GBN, 1), 256, SMEM_BYTES>>>(
        rst, DIM, W1, W1, W1, HID, hbuf, HID, DIM,
        b1, prelu, nullptr, nullptr, nullptr);

    // 5) FFN2 + bias + residual + LN2 -> out (fused epilogue)
    mm_tf32_kernel<2><<<dim3(N_NODES / GBM, 1, 1), 256, SMEM_BYTES>>>(
        hbuf, HID, W2, W2, W2, DIM, out, DIM, HID,
        b2, nullptr, rst, ln2g, ln2b);
}

// round 4
// speedup vs baseline: 1.8799x; 1.0475x over previous
#include <cuda_runtime.h>
#include <mma.h>
#include <math.h>

using namespace nvcuda;

#define N_NODES 40000
#define PAD_N   40064            // 313 * 128
#define N_EDGES 640000
#define DIM     128
#define QKV_LD  384
#define HID     512
#define LN_EPS  1e-5f

// ---------------- scratch (device globals; no allocation allowed) ----------
static __device__ float g_qkv[(size_t)PAD_N * QKV_LD];  // [q|k|v] per node
static __device__ float g_rst[(size_t)PAD_N * DIM];     // post-LN1
static __device__ float g_h  [(size_t)PAD_N * HID];     // FFN hidden
static __device__ int   g_off[N_NODES + 1];             // CSR offsets (by dst)
static __device__ int   g_cur[N_NODES];                 // counts / cursors
static __device__ int   g_esrc[N_EDGES];                // src node ids sorted by dst
static __device__ int   g_part[256];                    // scan partials

// ---------------- cp.async helpers -----------------------------------------
__device__ __forceinline__ void cp16(float* smem, const float* gmem)
{
    unsigned s = (unsigned)__cvta_generic_to_shared(smem);
    asm volatile("cp.async.ca.shared.global [%0], [%1], 16;\n" :: "r"(s), "l"(gmem));
}
__device__ __forceinline__ void cp16z(float* smem, const float* gmem, bool pred)
{
    unsigned s = (unsigned)__cvta_generic_to_shared(smem);
    int sz = pred ? 16 : 0;   // src-size 0 => zero-fill 16B, no gmem access
    asm volatile("cp.async.ca.shared.global [%0], [%1], 16, %2;\n"
                 :: "r"(s), "l"(gmem), "r"(sz));
}
#define CP_COMMIT() asm volatile("cp.async.commit_group;\n" ::)
#define CP_WAIT(n)  asm volatile("cp.async.wait_group %0;\n" :: "n"(n))

// ---------------- TF32 WMMA GEMM: C[M,N] = A[M,K] @ B[K,N] (row-major) -----
// Tile: BM=128, BN=128, BK=32, 2-stage cp.async double buffer, 2 blocks/SM.
// 8 warps in 4x2; warp tile 32x64 (2x4 wmma 16x16x8).
// EPI: 0 = plain store (QKV: B selected by blockIdx.z, C col offset z*128)
//      1 = +bias then PReLU
//      2 = +bias +residual, then per-row LayerNorm -> final output (row guard)
#define GBM 128
#define GBN 128
#define GBK 32
#define AS_F (GBM * 36)    // 4608 floats / stage
#define BS_F (GBK * 132)   // 4224 floats / stage
#define SMEM_BYTES (2 * (AS_F + BS_F) * 4)   // 70656 B

template <int EPI>
__global__ __launch_bounds__(256, 2)
void mm_tf32_kernel(const float* __restrict__ A, int lda, int Mlim,
                    const float* __restrict__ B0,
                    const float* __restrict__ B1,
                    const float* __restrict__ B2, int ldb,
                    float* __restrict__ C, int ldc, int K,
                    const float* __restrict__ bias,
                    const float* __restrict__ pw,
                    const float* __restrict__ res,
                    const float* __restrict__ lng,
                    const float* __restrict__ lnb)
{
    extern __shared__ __align__(16) float sm[];
    float (*Cs)[132] = (float(*)[132]) sm;        // epilogue reuse (128x132)

    const int tid = threadIdx.x;
    const int wid = tid >> 5;
    const int rowBase = blockIdx.x * GBM;
    const int colBaseB = blockIdx.y * GBN;
    const int z = blockIdx.z;
    const float* B = (z == 0) ? B0 : (z == 1) ? B1 : B2;
    const int colBaseC = colBaseB + z * 128;

    const int wm = wid >> 1;            // 0..3 -> warp row0 = wm*32
    const int wn = wid & 1;             // 0..1 -> warp col0 = wn*64

    wmma::fragment<wmma::accumulator, 16, 16, 8, float> acc[2][4];
#pragma unroll
    for (int i = 0; i < 2; i++)
#pragma unroll
        for (int j = 0; j < 4; j++) wmma::fill_fragment(acc[i][j], 0.f);

    const int ar = tid >> 3;            // 0..31 (4 passes of 32 rows)
    const int ac = (tid & 7) * 4;       // 0..28
    const int br = tid >> 5;            // 0..7  (4 passes of 8 rows)
    const int bc = (tid & 31) * 4;      // 0..124

    const float* Abase = A + (size_t)rowBase * lda;
    const float* Bbase = B + colBaseB;

    auto issue = [&](int st, int k0) {
        float* As = sm + st * AS_F;
        float* Bs = sm + 2 * AS_F + st * BS_F;
#pragma unroll
        for (int p = 0; p < 4; p++) {
            const int r = ar + p * 32;
            cp16z(As + r * 36 + ac, Abase + (size_t)r * lda + k0 + ac,
                  rowBase + r < Mlim);
        }
#pragma unroll
        for (int p = 0; p < 4; p++) {
            const int r = br + p * 8;
            cp16(Bs + r * 132 + bc, Bbase + (size_t)(k0 + r) * ldb + bc);
        }
        CP_COMMIT();
    };

    const int nIter = K / GBK;          // >= 4 always
    issue(0, 0);
    issue(1, GBK);

    for (int it = 0; it < nIter; it++) {
        if (it + 2 < nIter) { CP_WAIT(1); } else { CP_WAIT(0); }
        __syncthreads();

        const float* As = sm + (it & 1) * AS_F;
        const float* Bs = sm + 2 * AS_F + (it & 1) * BS_F;
#pragma unroll
        for (int kk = 0; kk < GBK; kk += 8) {
            wmma::fragment<wmma::matrix_a, 16, 16, 8, wmma::precision::tf32, wmma::row_major> fa[2];
            wmma::fragment<wmma::matrix_b, 16, 16, 8, wmma::precision::tf32, wmma::row_major> fb[4];
#pragma unroll
            for (int i = 0; i < 2; i++)
                wmma::load_matrix_sync(fa[i], As + (wm * 32 + i * 16) * 36 + kk, 36);
#pragma unroll
            for (int j = 0; j < 4; j++)
                wmma::load_matrix_sync(fb[j], Bs + kk * 132 + wn * 64 + j * 16, 132);
#pragma unroll
            for (int i = 0; i < 2; i++)
#pragma unroll
                for (int j = 0; j < 4; j++)
                    wmma::mma_sync(acc[i][j], fa[i], fb[j], acc[i][j]);
        }
        __syncthreads();
        if (it + 2 < nIter) issue(it & 1, (it + 2) * GBK);
    }

    // stage C tile in shared
#pragma unroll
    for (int i = 0; i < 2; i++)
#pragma unroll
        for (int j = 0; j < 4; j++)
            wmma::store_matrix_sync(&Cs[wm * 32 + i * 16][wn * 64 + j * 16],
                                    acc[i][j], 132, wmma::mem_row_major);
    __syncthreads();

    if (EPI == 0) {
#pragma unroll
        for (int it = 0; it < 16; it++) {
            const int lin = tid + it * 256;      // f4 index over 128x32
            const int r = lin >> 5, c4 = (lin & 31) * 4;
            *(float4*)(C + (size_t)(rowBase + r) * ldc + colBaseC + c4) =
                *(const float4*)&Cs[r][c4];
        }
    } else if (EPI == 1) {
#pragma unroll
        for (int it = 0; it < 16; it++) {
            const int lin = tid + it * 256;
            const int r = lin >> 5, c4 = (lin & 31) * 4;
            float4 v = *(const float4*)&Cs[r][c4];
            const float4 bi = *(const float4*)(bias + colBaseC + c4);
            const float4 pv = *(const float4*)(pw + colBaseC + c4);
            v.x += bi.x; v.y += bi.y; v.z += bi.z; v.w += bi.w;
            v.x = v.x >= 0.f ? v.x : pv.x * v.x;
            v.y = v.y >= 0.f ? v.y : pv.y * v.y;
            v.z = v.z >= 0.f ? v.z : pv.z * v.z;
            v.w = v.w >= 0.f ? v.w : pv.w * v.w;
            *(float4*)(C + (size_t)(rowBase + r) * ldc + colBaseC + c4) = v;
        }
    } else {  // EPI == 2 : +bias +residual, per-row LayerNorm -> out
        const int lane = tid & 31;
        const int col = lane * 4;
        const float4 bi = *(const float4*)(bias + col);
        const float4 g4 = *(const float4*)(lng + col);
        const float4 b4 = *(const float4*)(lnb + col);
#pragma unroll
        for (int rr = 0; rr < 16; rr++) {
            const int r = wid * 16 + rr;
            const int grow = rowBase + r;
            float4 v = *(const float4*)&Cs[r][col];
            const float4 rs = *(const float4*)(res + (size_t)grow * DIM + col);
            float x0 = v.x + bi.x + rs.x;
            float x1 = v.y + bi.y + rs.y;
            float x2 = v.z + bi.z + rs.z;
            float x3 = v.w + bi.w + rs.w;
            float sum = x0 + x1 + x2 + x3;
            float sq = x0 * x0 + x1 * x1 + x2 * x2 + x3 * x3;
#pragma unroll
            for (int o = 16; o; o >>= 1) {
                sum += __shfl_xor_sync(0xffffffffu, sum, o);
                sq  += __shfl_xor_sync(0xffffffffu, sq, o);
            }
            const float mu = sum * (1.f / DIM);
            const float var = sq * (1.f / DIM) - mu * mu;
            const float rstd = rsqrtf(var + LN_EPS);
            float4 o4;
            o4.x = (x0 - mu) * rstd * g4.x + b4.x;
            o4.y = (x1 - mu) * rstd * g4.y + b4.y;
            o4.z = (x2 - mu) * rstd * g4.z + b4.z;
            o4.w = (x3 - mu) * rstd * g4.w + b4.w;
            if (grow < N_NODES)
                *(float4*)(C + (size_t)grow * DIM + col) = o4;
        }
    }
}

// ---------------- CSR construction -----------------------------------------
__global__ void hist_kernel(const int* __restrict__ dst, int e)
{
    int i = blockIdx.x * blockDim.x + threadIdx.x;
    if (i < e) atomicAdd(&g_cur[dst[i]], 1);
}

#define SB 256
#define NSB ((N_NODES + SB - 1) / SB)   // 157

__global__ __launch_bounds__(SB)
void scan_blk_kernel(int n)
{
    __shared__ int sh[SB];
    const int t = threadIdx.x;
    const int i = blockIdx.x * SB + t;
    const int v = (i < n) ? g_cur[i] : 0;
    sh[t] = v;
    __syncthreads();
    for (int o = 1; o < SB; o <<= 1) {
        int x = (t >= o) ? sh[t - o] : 0;
        __syncthreads();
        sh[t] += x;
        __syncthreads();
    }
    if (i < n) g_off[i] = sh[t] - v;
    if (t == SB - 1) g_part[blockIdx.x] = sh[t];
}

__global__ __launch_bounds__(SB)
void scan_part_kernel(int nb, int n)
{
    __shared__ int sh[SB];
    const int t = threadIdx.x;
    const int v = (t < nb) ? g_part[t] : 0;
    sh[t] = v;
    __syncthreads();
    for (int o = 1; o < SB; o <<= 1) {
        int x = (t >= o) ? sh[t - o] : 0;
        __syncthreads();
        sh[t] += x;
        __syncthreads();
    }
    if (t < nb) g_part[t] = sh[t] - v;
    if (t == SB - 1) g_off[n] = sh[t];
}

__global__ __launch_bounds__(SB)
void scan_add_kernel(int n)
{
    const int i = blockIdx.x * SB + threadIdx.x;
    if (i < n) {
        const int o = g_off[i] + g_part[blockIdx.x];
        g_off[i] = o;
        g_cur[i] = o;
    }
}

// stores SRC node id directly (drops one gather level in attention)
__global__ void scatter_kernel(const int* __restrict__ src,
                               const int* __restrict__ dst, int e)
{
    int i = blockIdx.x * blockDim.x + threadIdx.x;
    if (i < e) {
        int p = atomicAdd(&g_cur[dst[i]], 1);
        g_esrc[p] = src[i];
    }
}

// ---------------- attention (warp per dst node, online softmax) + LN1 ------
__device__ __forceinline__ void attn_step(float4 k4, float4 v4, float4 q4,
                                          float& m, float& s, float4& acc)
{
    float x = q4.x * k4.x + q4.y * k4.y + q4.z * k4.z + q4.w * k4.w;
    x += __shfl_xor_sync(0xffffffffu, x, 1);
    x += __shfl_xor_sync(0xffffffffu, x, 2);
    x *= 0.08838834764831845f;              // 1/sqrt(DH*H) = 1/sqrt(128)
    const float nm = fmaxf(m, x);
    const float corr = __expf(m - nm);
    const float w = __expf(x - nm);
    s = s * corr + w;
    acc.x = acc.x * corr + w * v4.x;
    acc.y = acc.y * corr + w * v4.y;
    acc.z = acc.z * corr + w * v4.z;
    acc.w = acc.w * corr + w * v4.w;
    m = nm;
}

__global__ __launch_bounds__(256)
void attn_ln1_kernel(const float* __restrict__ feat,
                     const float* __restrict__ ln1g,
                     const float* __restrict__ ln1b)
{
    const int gw = (blockIdx.x * blockDim.x + threadIdx.x) >> 5;
    if (gw >= N_NODES) return;
    const int lane = threadIdx.x & 31;
    const int col = lane * 4;

    const float4 q4 = *(const float4*)(g_qkv + (size_t)gw * QKV_LD + col);

    float m = -INFINITY, s = 0.f;
    float4 acc = make_float4(0, 0, 0, 0);

    const int beg = g_off[gw], end = g_off[gw + 1];
    int t = beg;
    for (; t + 4 <= end; t += 4) {
        const int s0 = g_esrc[t],     s1 = g_esrc[t + 1];
        const int s2 = g_esrc[t + 2], s3 = g_esrc[t + 3];
        const float* b0 = g_qkv + (size_t)s0 * QKV_LD + col;
        const float* b1 = g_qkv + (size_t)s1 * QKV_LD + col;
        const float* b2 = g_qkv + (size_t)s2 * QKV_LD + col;
        const float* b3 = g_qkv + (size_t)s3 * QKV_LD + col;
        const float4 k0 = *(const float4*)(b0 + DIM);
        const float4 k1 = *(const float4*)(b1 + DIM);
        const float4 k2 = *(const float4*)(b2 + DIM);
        const float4 k3 = *(const float4*)(b3 + DIM);
        const float4 v0 = *(const float4*)(b0 + 2 * DIM);
        const float4 v1 = *(const float4*)(b1 + 2 * DIM);
        const float4 v2 = *(const float4*)(b2 + 2 * DIM);
        const float4 v3 = *(const float4*)(b3 + 2 * DIM);
        attn_step(k0, v0, q4, m, s, acc);
        attn_step(k1, v1, q4, m, s, acc);
        attn_step(k2, v2, q4, m, s, acc);
        attn_step(k3, v3, q4, m, s, acc);
    }
    for (; t < end; t++) {
        const float* b = g_qkv + (size_t)g_esrc[t] * QKV_LD + col;
        const float4 k4 = *(const float4*)(b + DIM);
        const float4 v4 = *(const float4*)(b + 2 * DIM);
        attn_step(k4, v4, q4, m, s, acc);
    }

    const float inv = (s > 0.f) ? (1.f / s) : 0.f;
    const float4 f4 = *(const float4*)(feat + (size_t)gw * DIM + col);
    float x0 = acc.x * inv + f4.x;
    float x1 = acc.y * inv + f4.y;
    float x2 = acc.z * inv + f4.z;
    float x3 = acc.w * inv + f4.w;

    float sum = x0 + x1 + x2 + x3;
    float sq = x0 * x0 + x1 * x1 + x2 * x2 + x3 * x3;
#pragma unroll
    for (int o = 16; o; o >>= 1) {
        sum += __shfl_xor_sync(0xffffffffu, sum, o);
        sq  += __shfl_xor_sync(0xffffffffu, sq, o);
    }
    const float mu = sum * (1.f / DIM);
    const float var = sq * (1.f / DIM) - mu * mu;
    const float rstd = rsqrtf(var + LN_EPS);

    const float4 g4 = *(const float4*)(ln1g + col);
    const float4 b4 = *(const float4*)(ln1b + col);
    float4 o4;
    o4.x = (x0 - mu) * rstd * g4.x + b4.x;
    o4.y = (x1 - mu) * rstd * g4.y + b4.y;
    o4.z = (x2 - mu) * rstd * g4.z + b4.z;
    o4.w = (x3 - mu) * rstd * g4.w + b4.w;
    *(float4*)(g_rst + (size_t)gw * DIM + col) = o4;
}

// ---------------- launch -----------------------------------------------------
extern "C" void kernel_launch(void* const* d_in, const int* in_sizes, int n_in,
                              void* d_out, int out_size)
{
    const float* feat  = (const float*)d_in[0];
    const int*   src   = (const int*)d_in[1];
    const int*   dst   = (const int*)d_in[2];
    const float* Wq    = (const float*)d_in[3];
    const float* Wk    = (const float*)d_in[4];
    const float* Wv    = (const float*)d_in[5];
    const float* ln1g  = (const float*)d_in[6];
    const float* ln1b  = (const float*)d_in[7];
    const float* ln2g  = (const float*)d_in[8];
    const float* ln2b  = (const float*)d_in[9];
    const float* W1    = (const float*)d_in[10];
    const float* b1    = (const float*)d_in[11];
    const float* prelu = (const float*)d_in[12];
    const float* W2    = (const float*)d_in[13];
    const float* b2    = (const float*)d_in[14];
    float* out = (float*)d_out;

    const int E = in_sizes[1];
    const int GX = PAD_N / GBM;   // 313

    void* p;
    float *qkv, *rst, *hbuf;
    int* curp;
    cudaGetSymbolAddress(&p, g_qkv); qkv  = (float*)p;
    cudaGetSymbolAddress(&p, g_rst); rst  = (float*)p;
    cudaGetSymbolAddress(&p, g_h);   hbuf = (float*)p;
    cudaGetSymbolAddress(&p, g_cur); curp = (int*)p;

    static bool init_done = false;
    static cudaStream_t s_side;
    static cudaEvent_t ev_fork, ev_join;
    if (!init_done) {
        cudaStreamCreateWithFlags(&s_side, cudaStreamNonBlocking);
        cudaEventCreateWithFlags(&ev_fork, cudaEventDisableTiming);
        cudaEventCreateWithFlags(&ev_join, cudaEventDisableTiming);
        cudaFuncSetAttribute(mm_tf32_kernel<0>, cudaFuncAttributeMaxDynamicSharedMemorySize, SMEM_BYTES);
        cudaFuncSetAttribute(mm_tf32_kernel<1>, cudaFuncAttributeMaxDynamicSharedMemorySize, SMEM_BYTES);
        cudaFuncSetAttribute(mm_tf32_kernel<2>, cudaFuncAttributeMaxDynamicSharedMemorySize, SMEM_BYTES);
        init_done = true;
    }

    // fork: CSR construction on side stream, concurrent with QKV GEMM
    cudaEventRecord(ev_fork, 0);
    cudaStreamWaitEvent(s_side, ev_fork, 0);

    // 1) fused QKV projections (TF32 tensor cores), one launch, grid.z = 3
    mm_tf32_kernel<0><<<dim3(GX, 1, 3), 256, SMEM_BYTES>>>(
        feat, DIM, N_NODES, Wq, Wk, Wv, DIM, qkv, QKV_LD, DIM,
        nullptr, nullptr, nullptr, nullptr, nullptr);

    // 2) CSR by dst (side stream)
    cudaMemsetAsync(curp, 0, N_NODES * sizeof(int), s_side);
    hist_kernel<<<(E + 255) / 256, 256, 0, s_side>>>(dst, E);
    scan_blk_kernel<<<NSB, SB, 0, s_side>>>(N_NODES);
    scan_part_kernel<<<1, SB, 0, s_side>>>(NSB, N_NODES);
    scan_add_kernel<<<NSB, SB, 0, s_side>>>(N_NODES);
    scatter_kernel<<<(E + 255) / 256, 256, 0, s_side>>>(src, dst, E);

    // join
    cudaEventRecord(ev_join, s_side);
    cudaStreamWaitEvent(0, ev_join, 0);

    // 3) online-softmax attention + residual + LN1 (warp per dst node)
    attn_ln1_kernel<<<(N_NODES * 32 + 255) / 256, 256>>>(feat, ln1g, ln1b);

    // 4) FFN1: h = PReLU(rst@W1 + b1)
    mm_tf32_kernel<1><<<dim3(GX, HID / GBN, 1), 256, SMEM_BYTES>>>(
        rst, DIM, PAD_N, W1, W1, W1, HID, hbuf, HID, DIM,
        b1, prelu, nullptr, nullptr, nullptr);

    // 5) FFN2 + bias + residual + LN2 -> out (fused epilogue)
    mm_tf32_kernel<2><<<dim3(GX, 1, 1), 256, SMEM_BYTES>>>(
        hbuf, HID, PAD_N, W2, W2, W2, DIM, out, DIM, HID,
        b2, nullptr, rst, ln2g, ln2b);
}